// round 2
// baseline (speedup 1.0000x reference)
#include <cuda_runtime.h>
#include <cuda_fp16.h>
#include <cstdint>
#include <cstddef>

// Problem constants
#define BATCH 64
#define TT    512
#define HH    1024
#define NB    128      // persistent CTAs (4 gemms x 32 n-blocks)
#define NTHR  256
#define KC    32       // K-chunk (halves)
#define NCHUNK 64      // 2048 / 32
#define RS    40       // smem row stride in halves (KC + 8 pad; 80B, conflict-free, 16B-aligned)

// ---------------- device scratch (static __device__ globals are the sanctioned scratch) ----
static __device__ __half g_W[(size_t)4 * 4096 * 2048];   // fused+permuted weights, fp16 (64 MB)
static __device__ float  g_bias[4 * 4096];               // bih+bhh fused, permuted
static __device__ __half g_x16[(size_t)TT * BATCH * HH]; // x transposed to [t][b][k], fp16 (64 MB)
static __device__ __half g_h0[2][BATCH * HH];            // carry h (layer0 backward), ping-pong
static __device__ float  g_c0[2][BATCH * HH];
static __device__ __half g_h1[2][BATCH * HH];            // carry h (layer1 backward)
static __device__ float  g_c1[2][BATCH * HH];
static __device__ __half g_hf0[2][BATCH * HH];           // layer0 forward h -> layer1 input
static __device__ unsigned g_bar_arrive;
static __device__ unsigned g_bar_gen;

// ---------------- small PTX helpers ----------------
__device__ __forceinline__ void cp16(unsigned saddr, const void* gptr) {
    asm volatile("cp.async.cg.shared.global [%0], [%1], 16;\n" :: "r"(saddr), "l"(gptr));
}
__device__ __forceinline__ void cp_commit() {
    asm volatile("cp.async.commit_group;\n" ::: "memory");
}
__device__ __forceinline__ void cp_wait0() {
    asm volatile("cp.async.wait_group 0;\n" ::: "memory");
}
__device__ __forceinline__ void mma16816(float* d, const unsigned* a, const unsigned* b) {
    asm volatile(
        "mma.sync.aligned.m16n8k16.row.col.f32.f16.f16.f32 "
        "{%0,%1,%2,%3}, {%4,%5,%6,%7}, {%8,%9}, {%0,%1,%2,%3};\n"
        : "+f"(d[0]), "+f"(d[1]), "+f"(d[2]), "+f"(d[3])
        : "r"(a[0]), "r"(a[1]), "r"(a[2]), "r"(a[3]), "r"(b[0]), "r"(b[1]));
}

// Cumulative-counter grid barrier (reset by k_init each launch; deterministic across replays).
__device__ __forceinline__ void gridbar(int target) {
    __syncthreads();
    __threadfence();                       // publish this CTA's global writes
    if (threadIdx.x == 0) {
        unsigned my = atomicAdd(&g_bar_arrive, 1u) + 1u;
        if (my == (unsigned)(NB * target)) {
            atomicExch(&g_bar_gen, (unsigned)target);
        } else {
            volatile unsigned* vg = &g_bar_gen;
            while (*vg < (unsigned)target) { }
        }
    }
    __syncthreads();
}

// ---------------- preprocessing kernels ----------------
// Zero all recurrent state (both parities) + barrier counters.
__global__ void k_init() {
    int i = blockIdx.x * blockDim.x + threadIdx.x;
    if (i == 0) { g_bar_arrive = 0u; g_bar_gen = 0u; }
    if (i < 2 * BATCH * HH) {
        ((unsigned short*)g_h0)[i]  = 0;
        ((unsigned short*)g_h1)[i]  = 0;
        ((unsigned short*)g_hf0)[i] = 0;
        ((float*)g_c0)[i] = 0.f;
        ((float*)g_c1)[i] = 0.f;
    }
}

// Build fused fp16 weights. GEMM g in {0:f0, 1:b0, 2:f1, 3:b1}. Output layout:
// g_W[g][n'][k], n' = ncta*128 + gate*32 + u  (so each CTA owns 32 hidden units, all 4 gates),
// k in [0,1024) from Wih (K-reversed for g==1: folds the feature reversal of x), else Whh.
__global__ void k_prep_w(const float* __restrict__ Wih_f, const float* __restrict__ Whh_f,
                         const float* __restrict__ Wih_b, const float* __restrict__ Whh_b) {
    const size_t total = (size_t)4 * 4096 * 2048;
    for (size_t idx = (size_t)blockIdx.x * blockDim.x + threadIdx.x; idx < total;
         idx += (size_t)gridDim.x * blockDim.x) {
        int k  = (int)(idx & 2047);
        int np = (int)((idx >> 11) & 4095);
        int gm = (int)(idx >> 23);
        int gate = (np & 127) >> 5;
        int u    = np & 31;
        int nct  = np >> 7;
        int n = gate * 1024 + nct * 32 + u;
        int layer = gm >> 1;
        bool bwd  = (gm & 1) != 0;
        const float* Wih = bwd ? Wih_b : Wih_f;
        const float* Whh = bwd ? Whh_b : Whh_f;
        float v;
        if (k < 1024) {
            int kk = (gm == 1) ? (1023 - k) : k;   // fold x feature-reversal (layer-0 backward only)
            v = Wih[((size_t)layer * 4096 + n) * 1024 + kk];
        } else {
            v = Whh[((size_t)layer * 4096 + n) * 1024 + (k - 1024)];
        }
        g_W[idx] = __float2half_rn(v);
    }
}

__global__ void k_prep_b(const float* __restrict__ bih_f, const float* __restrict__ bhh_f,
                         const float* __restrict__ bih_b, const float* __restrict__ bhh_b) {
    int idx = blockIdx.x * blockDim.x + threadIdx.x;
    if (idx < 4 * 4096) {
        int np = idx & 4095, gm = idx >> 12;
        int gate = (np & 127) >> 5, u = np & 31, nct = np >> 7;
        int n = gate * 1024 + nct * 32 + u;
        int layer = gm >> 1;
        bool bwd = (gm & 1) != 0;
        const float* bi = bwd ? bih_b : bih_f;
        const float* bh = bwd ? bhh_b : bhh_f;
        g_bias[idx] = bi[layer * 4096 + n] + bh[layer * 4096 + n];
    }
}

// x (B,T,H) fp32 -> g_x16[t][b][k] fp16 (contiguous per-step A source)
__global__ void k_prep_x(const float* __restrict__ x) {
    const size_t total = (size_t)TT * BATCH * HH;
    for (size_t idx = (size_t)blockIdx.x * blockDim.x + threadIdx.x; idx < total;
         idx += (size_t)gridDim.x * blockDim.x) {
        int k = (int)(idx & 1023);
        int b = (int)((idx >> 10) & 63);
        int t = (int)(idx >> 16);
        g_x16[idx] = __float2half_rn(x[((size_t)b * TT + t) * HH + k]);
    }
}

// ---------------- persistent LSTM kernel ----------------
// Grid = 128 CTAs: gemm g = blockIdx.x>>5 in {f0,b0,f1,b1}; ncta = blockIdx.x&31 owns N-block of 128
// (= 32 hidden units x 4 gates). Iteration i: layer0(t=i) || layer1(t=i-1); 1 grid barrier per iter.
__global__ void __launch_bounds__(NTHR, 1) k_lstm(float* __restrict__ dout) {
    __shared__ __align__(16) unsigned char smraw[34048];
    __half* A_s = (__half*)smraw;                 // 2 bufs * 64 * RS = 5120 halves
    __half* W_s = (__half*)smraw + 2 * 64 * RS;   // 2 bufs * 128 * RS = 10240 halves
    float*  gsm = (float*)smraw;                  // overlay: 64 x 132 fp32 gates (after GEMM)

    const int tid  = threadIdx.x;
    const int lane = tid & 31;
    const int warp = tid >> 5;
    const int m0 = (warp >> 2) * 32;   // warp tile: 32(m) x 32(n)
    const int n0 = (warp & 3) * 32;
    const int gm   = blockIdx.x >> 5;
    const int nct  = blockIdx.x & 31;

    const __half* wbase = g_W + ((size_t)(gm * 4096 + nct * 128)) * 2048;
    const float*  bp    = g_bias + gm * 4096 + nct * 128;

    float* out   = dout;
    float* cout  = dout + (size_t)67108864;   // B*T*2H
    float* outL  = dout + (size_t)134217728;  // 2*B*T*2H
    float* coutL = outL + 131072;             // B*2H

    for (int it = 0; it <= TT; ++it) {
        const int ri = it & 1, wi = ri ^ 1;
        const bool active = (gm < 2) ? (it < TT) : (it >= 1);
        if (active) {
            const int t = (gm < 2) ? it : (it - 1);
            const __half* a1;
            const __half* a2;
            if (gm < 2)       { a1 = g_x16 + (size_t)t * (BATCH * HH); a2 = g_h0[ri]; }
            else if (gm == 2) { a1 = g_hf0[ri];                        a2 = g_h1[ri]; }
            else              { a1 = g_h0[ri];                         a2 = g_h1[ri]; }

            float acc[2][4][4];
            #pragma unroll
            for (int a = 0; a < 2; ++a)
                #pragma unroll
                for (int b = 0; b < 4; ++b)
                    #pragma unroll
                    for (int c = 0; c < 4; ++c) acc[a][b][c] = 0.f;

            // ---- prologue: load chunk 0 ----
            {
                const __half* asrc = a1;  // chunk 0 always in first half
                int row = tid >> 2, seg = tid & 3;
                cp16((unsigned)__cvta_generic_to_shared(A_s + row * RS + seg * 8),
                     asrc + row * HH + seg * 8);
                #pragma unroll
                for (int j = 0; j < 2; ++j) {
                    int idx = tid + j * NTHR;
                    int wr = idx >> 2, ws = idx & 3;
                    cp16((unsigned)__cvta_generic_to_shared(W_s + wr * RS + ws * 8),
                         wbase + (size_t)wr * 2048 + ws * 8);
                }
                cp_commit();
            }

            // ---- K loop: 64 chunks, double-buffered cp.async ----
            for (int kc = 0; kc < NCHUNK; ++kc) {
                cp_wait0();
                __syncthreads();   // chunk kc landed; all warps done with mma(kc-1)
                if (kc + 1 < NCHUNK) {
                    const int nk = kc + 1;
                    const int nbuf = nk & 1;
                    const __half* asrc = (nk < 32) ? (a1 + nk * KC) : (a2 + (nk - 32) * KC);
                    int row = tid >> 2, seg = tid & 3;
                    cp16((unsigned)__cvta_generic_to_shared(A_s + nbuf * 64 * RS + row * RS + seg * 8),
                         asrc + row * HH + seg * 8);
                    const __half* wsrc = wbase + nk * KC;
                    #pragma unroll
                    for (int j = 0; j < 2; ++j) {
                        int idx = tid + j * NTHR;
                        int wr = idx >> 2, ws = idx & 3;
                        cp16((unsigned)__cvta_generic_to_shared(W_s + nbuf * 128 * RS + wr * RS + ws * 8),
                             wsrc + (size_t)wr * 2048 + ws * 8);
                    }
                    cp_commit();
                }
                const __half* Ab = A_s + (kc & 1) * 64 * RS;
                const __half* Wb = W_s + (kc & 1) * 128 * RS;
                #pragma unroll
                for (int ks = 0; ks < 2; ++ks) {
                    const int kk = ks * 16 + ((lane & 3) << 1);
                    unsigned af[2][4], bf[4][2];
                    #pragma unroll
                    for (int mt = 0; mt < 2; ++mt) {
                        int r = m0 + mt * 16 + (lane >> 2);
                        af[mt][0] = *(const unsigned*)(Ab + r * RS + kk);
                        af[mt][1] = *(const unsigned*)(Ab + (r + 8) * RS + kk);
                        af[mt][2] = *(const unsigned*)(Ab + r * RS + kk + 8);
                        af[mt][3] = *(const unsigned*)(Ab + (r + 8) * RS + kk + 8);
                    }
                    #pragma unroll
                    for (int nt = 0; nt < 4; ++nt) {
                        int rw = n0 + nt * 8 + (lane >> 2);
                        bf[nt][0] = *(const unsigned*)(Wb + rw * RS + kk);
                        bf[nt][1] = *(const unsigned*)(Wb + rw * RS + kk + 8);
                    }
                    #pragma unroll
                    for (int mt = 0; mt < 2; ++mt)
                        #pragma unroll
                        for (int nt = 0; nt < 4; ++nt)
                            mma16816(acc[mt][nt], af[mt], bf[nt]);
                }
            }
            __syncthreads();  // all mma reads done before gates overlay

            // ---- gates to smem (fp32, row stride 132) ----
            #pragma unroll
            for (int mt = 0; mt < 2; ++mt)
                #pragma unroll
                for (int nt = 0; nt < 4; ++nt)
                    #pragma unroll
                    for (int r = 0; r < 4; ++r) {
                        int row = m0 + mt * 16 + (lane >> 2) + ((r & 2) ? 8 : 0);
                        int col = n0 + nt * 8 + ((lane & 3) << 1) + (r & 1);
                        gsm[row * 132 + col] = acc[mt][nt][r];
                    }
            __syncthreads();

            // ---- cell epilogue: 64 batches x 32 hidden units owned by this CTA ----
            for (int idx = tid; idx < BATCH * 32; idx += NTHR) {
                int bb = idx >> 5, ul = idx & 31;
                int uglob = nct * 32 + ul;
                int s = bb * HH + uglob;
                float gi = gsm[bb * 132 + ul]      + bp[ul];
                float gf = gsm[bb * 132 + 32 + ul] + bp[32 + ul];
                float gg = gsm[bb * 132 + 64 + ul] + bp[64 + ul];
                float go = gsm[bb * 132 + 96 + ul] + bp[96 + ul];
                float si = 1.f / (1.f + __expf(-gi));
                float sf = 1.f / (1.f + __expf(-gf));
                float so = 1.f / (1.f + __expf(-go));
                float tg = tanhf(gg);
                float cp_ = (gm < 2) ? __ldcg(&g_c0[ri][s]) : __ldcg(&g_c1[ri][s]);  // L2-coherent
                float cn = sf * cp_ + si * tg;
                float h  = so * tanhf(cn);
                if (gm == 0) {
                    g_hf0[wi][s] = __float2half_rn(h);
                } else if (gm == 1) {
                    g_h0[wi][s] = __float2half_rn(h);
                    g_c0[wi][s] = cn;
                } else {
                    size_t ob = ((size_t)bb * TT + t) * 2048 + (gm == 3 ? 1024 : 0) + uglob;
                    out[ob]  = h;
                    cout[ob] = cn;
                    if (t == TT - 1) {
                        int o2 = bb * 2048 + (gm == 3 ? 1024 : 0) + uglob;
                        outL[o2]  = h;
                        coutL[o2] = cn;
                    }
                    if (gm == 3) {
                        g_h1[wi][s] = __float2half_rn(h);
                        g_c1[wi][s] = cn;
                    }
                }
            }
        }
        gridbar(it + 1);
    }
}

// ---------------- launcher ----------------
extern "C" void kernel_launch(void* const* d_in, const int* in_sizes, int n_in,
                              void* d_out, int out_size) {
    (void)in_sizes; (void)n_in; (void)out_size;
    const float* x     = (const float*)d_in[0];
    const float* Wih_f = (const float*)d_in[1];
    const float* Whh_f = (const float*)d_in[2];
    const float* bih_f = (const float*)d_in[3];
    const float* bhh_f = (const float*)d_in[4];
    const float* Wih_b = (const float*)d_in[5];
    const float* Whh_b = (const float*)d_in[6];
    const float* bih_b = (const float*)d_in[7];
    const float* bhh_b = (const float*)d_in[8];

    k_init<<<512, 256>>>();
    k_prep_w<<<8192, 256>>>(Wih_f, Whh_f, Wih_b, Whh_b);
    k_prep_b<<<64, 256>>>(bih_f, bhh_f, bih_b, bhh_b);
    k_prep_x<<<8192, 256>>>(x);
    k_lstm<<<NB, NTHR>>>((float*)d_out);
}

// round 3
// speedup vs baseline: 1.3607x; 1.3607x over previous
#include <cuda_runtime.h>
#include <cuda_fp16.h>
#include <cstdint>
#include <cstddef>

// Problem constants
#define BATCH 64
#define TT    512
#define HH    1024
#define NB    128      // persistent CTAs (4 gemms x 32 n-blocks)
#define NTHR  256
#define KC    64       // K-chunk (halves)
#define NCHUNK 32      // 2048 / 64
#define NSTAGE 4       // cp.async pipeline stages
#define RS    72       // smem row stride in halves (KC + 8 pad; 144B = 9*16B, conflict-free)
#define SMEM_BYTES (NSTAGE * (64 + 128) * RS * 2)   // 110592

// ---------------- device scratch ----------------
static __device__ __half g_W[(size_t)4 * 4096 * 2048];   // fused+permuted weights, fp16 (64 MB)
static __device__ float  g_bias[4 * 4096];               // bih+bhh fused, permuted
static __device__ __half g_x16[(size_t)TT * BATCH * HH]; // x as [t][b][k], fp16 (64 MB)
static __device__ __half g_h0[2][BATCH * HH];            // carry h (layer0 backward), ping-pong
static __device__ float  g_c0[2][BATCH * HH];
static __device__ __half g_h1[2][BATCH * HH];            // carry h (layer1 backward)
static __device__ float  g_c1[2][BATCH * HH];
static __device__ __half g_hf0[2][BATCH * HH];           // layer0 forward h -> layer1 input
static __device__ unsigned g_bar_arrive;
static __device__ unsigned g_bar_gen;

// ---------------- PTX helpers ----------------
__device__ __forceinline__ void cp16(unsigned saddr, const void* gptr) {
    asm volatile("cp.async.cg.shared.global [%0], [%1], 16;\n" :: "r"(saddr), "l"(gptr));
}
__device__ __forceinline__ void cp_commit() {
    asm volatile("cp.async.commit_group;\n" ::: "memory");
}
__device__ __forceinline__ void cp_wait2() {
    asm volatile("cp.async.wait_group 2;\n" ::: "memory");
}
__device__ __forceinline__ void mma16816(float* d, const unsigned* a, const unsigned* b) {
    asm volatile(
        "mma.sync.aligned.m16n8k16.row.col.f32.f16.f16.f32 "
        "{%0,%1,%2,%3}, {%4,%5,%6,%7}, {%8,%9}, {%0,%1,%2,%3};\n"
        : "+f"(d[0]), "+f"(d[1]), "+f"(d[2]), "+f"(d[3])
        : "r"(a[0]), "r"(a[1]), "r"(a[2]), "r"(a[3]), "r"(b[0]), "r"(b[1]));
}

// Cumulative-counter grid barrier (reset by k_init each launch).
__device__ __forceinline__ void gridbar(int target) {
    __syncthreads();
    __threadfence();
    if (threadIdx.x == 0) {
        unsigned my = atomicAdd(&g_bar_arrive, 1u) + 1u;
        if (my == (unsigned)(NB * target)) {
            atomicExch(&g_bar_gen, (unsigned)target);
        } else {
            volatile unsigned* vg = &g_bar_gen;
            while (*vg < (unsigned)target) { }
        }
    }
    __syncthreads();
}

// ---------------- preprocessing kernels ----------------
__global__ void k_init() {
    int i = blockIdx.x * blockDim.x + threadIdx.x;
    if (i == 0) { g_bar_arrive = 0u; g_bar_gen = 0u; }
    if (i < 2 * BATCH * HH) {
        ((unsigned short*)g_h0)[i]  = 0;
        ((unsigned short*)g_h1)[i]  = 0;
        ((unsigned short*)g_hf0)[i] = 0;
        ((float*)g_c0)[i] = 0.f;
        ((float*)g_c1)[i] = 0.f;
    }
}

// Fused fp16 weights. GEMM g in {0:f0, 1:b0, 2:f1, 3:b1}. Layout:
// g_W[g][n'][k], n' = ncta*128 + gate*32 + u; k<1024 from Wih (K-reversed for g==1), else Whh.
__global__ void k_prep_w(const float* __restrict__ Wih_f, const float* __restrict__ Whh_f,
                         const float* __restrict__ Wih_b, const float* __restrict__ Whh_b) {
    const size_t total = (size_t)4 * 4096 * 2048;
    for (size_t idx = (size_t)blockIdx.x * blockDim.x + threadIdx.x; idx < total;
         idx += (size_t)gridDim.x * blockDim.x) {
        int k  = (int)(idx & 2047);
        int np = (int)((idx >> 11) & 4095);
        int gm = (int)(idx >> 23);
        int gate = (np & 127) >> 5;
        int u    = np & 31;
        int nct  = np >> 7;
        int n = gate * 1024 + nct * 32 + u;
        int layer = gm >> 1;
        bool bwd  = (gm & 1) != 0;
        const float* Wih = bwd ? Wih_b : Wih_f;
        const float* Whh = bwd ? Whh_b : Whh_f;
        float v;
        if (k < 1024) {
            int kk = (gm == 1) ? (1023 - k) : k;   // fold x feature-reversal
            v = Wih[((size_t)layer * 4096 + n) * 1024 + kk];
        } else {
            v = Whh[((size_t)layer * 4096 + n) * 1024 + (k - 1024)];
        }
        g_W[idx] = __float2half_rn(v);
    }
}

__global__ void k_prep_b(const float* __restrict__ bih_f, const float* __restrict__ bhh_f,
                         const float* __restrict__ bih_b, const float* __restrict__ bhh_b) {
    int idx = blockIdx.x * blockDim.x + threadIdx.x;
    if (idx < 4 * 4096) {
        int np = idx & 4095, gm = idx >> 12;
        int gate = (np & 127) >> 5, u = np & 31, nct = np >> 7;
        int n = gate * 1024 + nct * 32 + u;
        int layer = gm >> 1;
        bool bwd = (gm & 1) != 0;
        const float* bi = bwd ? bih_b : bih_f;
        const float* bh = bwd ? bhh_b : bhh_f;
        g_bias[idx] = bi[layer * 4096 + n] + bh[layer * 4096 + n];
    }
}

__global__ void k_prep_x(const float* __restrict__ x) {
    const size_t total = (size_t)TT * BATCH * HH;
    for (size_t idx = (size_t)blockIdx.x * blockDim.x + threadIdx.x; idx < total;
         idx += (size_t)gridDim.x * blockDim.x) {
        int k = (int)(idx & 1023);
        int b = (int)((idx >> 10) & 63);
        int t = (int)(idx >> 16);
        g_x16[idx] = __float2half_rn(x[((size_t)b * TT + t) * HH + k]);
    }
}

// ---------------- persistent LSTM kernel ----------------
// 128 CTAs: gemm gm = blockIdx.x>>5 in {f0,b0,f1,b1}; nct = blockIdx.x&31 owns N-block of 128.
// Iteration it: layer0(t=it) || layer1(t=it-1); 1 grid barrier per iteration.
__global__ void __launch_bounds__(NTHR, 1) k_lstm(float* __restrict__ dout) {
    extern __shared__ __align__(16) unsigned char smraw[];
    __half* A_s = (__half*)smraw;                          // NSTAGE * 64 * RS halves
    __half* W_s = (__half*)smraw + NSTAGE * 64 * RS;       // NSTAGE * 128 * RS halves
    float*  gsm = (float*)smraw;                           // overlay: 64 x 132 fp32 gates

    const int tid  = threadIdx.x;
    const int lane = tid & 31;
    const int warp = tid >> 5;
    const int m0 = (warp >> 2) * 32;   // warp tile: 32(m) x 32(n)
    const int n0 = (warp & 3) * 32;
    const int gm   = blockIdx.x >> 5;
    const int nct  = blockIdx.x & 31;

    const __half* wbase = g_W + ((size_t)(gm * 4096 + nct * 128)) * 2048;
    const float*  bp    = g_bias + gm * 4096 + nct * 128;

    float* out   = dout;
    float* cout  = dout + (size_t)67108864;   // B*T*2H
    float* outL  = dout + (size_t)134217728;  // 2*B*T*2H
    float* coutL = outL + 131072;             // B*2H

    for (int it = 0; it <= TT; ++it) {
        const int ri = it & 1, wi = ri ^ 1;
        const bool active = (gm < 2) ? (it < TT) : (it >= 1);
        if (active) {
            const int t = (gm < 2) ? it : (it - 1);
            const __half* a1;
            const __half* a2;
            if (gm < 2)       { a1 = g_x16 + (size_t)t * (BATCH * HH); a2 = g_h0[ri]; }
            else if (gm == 2) { a1 = g_hf0[ri];                        a2 = g_h1[ri]; }
            else              { a1 = g_h0[ri];                         a2 = g_h1[ri]; }

            float acc[2][4][4];
            #pragma unroll
            for (int a = 0; a < 2; ++a)
                #pragma unroll
                for (int b = 0; b < 4; ++b)
                    #pragma unroll
                    for (int c = 0; c < 4; ++c) acc[a][b][c] = 0.f;

            // ---- prologue: stage chunks 0..NSTAGE-2 (3 groups) ----
            #pragma unroll
            for (int pc = 0; pc < NSTAGE - 1; ++pc) {
                const __half* asrc = (pc < 16) ? (a1 + pc * KC) : (a2 + (pc - 16) * KC);
                const __half* wsrc = wbase + pc * KC;
                __half* Ad = A_s + pc * 64 * RS;
                __half* Wd = W_s + pc * 128 * RS;
                #pragma unroll
                for (int j = 0; j < 2; ++j) {
                    int idx = tid + j * NTHR;             // 512 ops: A 64 rows x 8 segs
                    int row = idx >> 3, seg = idx & 7;
                    cp16((unsigned)__cvta_generic_to_shared(Ad + row * RS + seg * 8),
                         asrc + row * HH + seg * 8);
                }
                #pragma unroll
                for (int j = 0; j < 4; ++j) {
                    int idx = tid + j * NTHR;             // 1024 ops: W 128 rows x 8 segs
                    int row = idx >> 3, seg = idx & 7;
                    cp16((unsigned)__cvta_generic_to_shared(Wd + row * RS + seg * 8),
                         wsrc + (size_t)row * 2048 + seg * 8);
                }
                cp_commit();
            }

            // ---- K loop: 32 chunks, 4-stage pipeline, one commit per iteration ----
            for (int kc = 0; kc < NCHUNK; ++kc) {
                cp_wait2();        // chunk kc landed (2 groups still in flight)
                __syncthreads();   // all warps: chunk kc visible; done with chunk kc-1's buffer
                {
                    const int nk = kc + NSTAGE - 1;
                    if (nk < NCHUNK) {
                        const int nbuf = nk & (NSTAGE - 1);
                        const __half* asrc = (nk < 16) ? (a1 + nk * KC) : (a2 + (nk - 16) * KC);
                        const __half* wsrc = wbase + nk * KC;
                        __half* Ad = A_s + nbuf * 64 * RS;
                        __half* Wd = W_s + nbuf * 128 * RS;
                        #pragma unroll
                        for (int j = 0; j < 2; ++j) {
                            int idx = tid + j * NTHR;
                            int row = idx >> 3, seg = idx & 7;
                            cp16((unsigned)__cvta_generic_to_shared(Ad + row * RS + seg * 8),
                                 asrc + row * HH + seg * 8);
                        }
                        #pragma unroll
                        for (int j = 0; j < 4; ++j) {
                            int idx = tid + j * NTHR;
                            int row = idx >> 3, seg = idx & 7;
                            cp16((unsigned)__cvta_generic_to_shared(Wd + row * RS + seg * 8),
                                 wsrc + (size_t)row * 2048 + seg * 8);
                        }
                    }
                    cp_commit();   // ALWAYS commit (possibly-empty group keeps counts uniform)
                }
                const __half* Ab = A_s + (kc & (NSTAGE - 1)) * 64 * RS;
                const __half* Wb = W_s + (kc & (NSTAGE - 1)) * 128 * RS;
                #pragma unroll
                for (int ks = 0; ks < 4; ++ks) {
                    const int kk = ks * 16 + ((lane & 3) << 1);
                    unsigned af[2][4], bf[4][2];
                    #pragma unroll
                    for (int mt = 0; mt < 2; ++mt) {
                        int r = m0 + mt * 16 + (lane >> 2);
                        af[mt][0] = *(const unsigned*)(Ab + r * RS + kk);
                        af[mt][1] = *(const unsigned*)(Ab + (r + 8) * RS + kk);
                        af[mt][2] = *(const unsigned*)(Ab + r * RS + kk + 8);
                        af[mt][3] = *(const unsigned*)(Ab + (r + 8) * RS + kk + 8);
                    }
                    #pragma unroll
                    for (int nt = 0; nt < 4; ++nt) {
                        int rw = n0 + nt * 8 + (lane >> 2);
                        bf[nt][0] = *(const unsigned*)(Wb + rw * RS + kk);
                        bf[nt][1] = *(const unsigned*)(Wb + rw * RS + kk + 8);
                    }
                    #pragma unroll
                    for (int mt = 0; mt < 2; ++mt)
                        #pragma unroll
                        for (int nt = 0; nt < 4; ++nt)
                            mma16816(acc[mt][nt], af[mt], bf[nt]);
                }
            }
            __syncthreads();  // all mma reads done before gates overlay

            // ---- gates to smem (fp32, row stride 132) ----
            #pragma unroll
            for (int mt = 0; mt < 2; ++mt)
                #pragma unroll
                for (int nt = 0; nt < 4; ++nt)
                    #pragma unroll
                    for (int r = 0; r < 4; ++r) {
                        int row = m0 + mt * 16 + (lane >> 2) + ((r & 2) ? 8 : 0);
                        int col = n0 + nt * 8 + ((lane & 3) << 1) + (r & 1);
                        gsm[row * 132 + col] = acc[mt][nt][r];
                    }
            __syncthreads();

            // ---- cell epilogue: 64 batches x 32 hidden units ----
            for (int idx = tid; idx < BATCH * 32; idx += NTHR) {
                int bb = idx >> 5, ul = idx & 31;
                int uglob = nct * 32 + ul;
                int s = bb * HH + uglob;
                float gi = gsm[bb * 132 + ul]      + bp[ul];
                float gf = gsm[bb * 132 + 32 + ul] + bp[32 + ul];
                float gg = gsm[bb * 132 + 64 + ul] + bp[64 + ul];
                float go = gsm[bb * 132 + 96 + ul] + bp[96 + ul];
                float si = 1.f / (1.f + __expf(-gi));
                float sf = 1.f / (1.f + __expf(-gf));
                float so = 1.f / (1.f + __expf(-go));
                float tg = tanhf(gg);
                float cp_ = (gm < 2) ? __ldcg(&g_c0[ri][s]) : __ldcg(&g_c1[ri][s]);
                float cn = sf * cp_ + si * tg;
                float h  = so * tanhf(cn);
                if (gm == 0) {
                    g_hf0[wi][s] = __float2half_rn(h);
                } else if (gm == 1) {
                    g_h0[wi][s] = __float2half_rn(h);
                    g_c0[wi][s] = cn;
                } else {
                    size_t ob = ((size_t)bb * TT + t) * 2048 + (gm == 3 ? 1024 : 0) + uglob;
                    out[ob]  = h;
                    cout[ob] = cn;
                    if (t == TT - 1) {
                        int o2 = bb * 2048 + (gm == 3 ? 1024 : 0) + uglob;
                        outL[o2]  = h;
                        coutL[o2] = cn;
                    }
                    if (gm == 3) {
                        g_h1[wi][s] = __float2half_rn(h);
                        g_c1[wi][s] = cn;
                    }
                }
            }
        }
        gridbar(it + 1);
    }
}

// ---------------- launcher ----------------
extern "C" void kernel_launch(void* const* d_in, const int* in_sizes, int n_in,
                              void* d_out, int out_size) {
    (void)in_sizes; (void)n_in; (void)out_size;
    const float* x     = (const float*)d_in[0];
    const float* Wih_f = (const float*)d_in[1];
    const float* Whh_f = (const float*)d_in[2];
    const float* bih_f = (const float*)d_in[3];
    const float* bhh_f = (const float*)d_in[4];
    const float* Wih_b = (const float*)d_in[5];
    const float* Whh_b = (const float*)d_in[6];
    const float* bih_b = (const float*)d_in[7];
    const float* bhh_b = (const float*)d_in[8];

    cudaFuncSetAttribute(k_lstm, cudaFuncAttributeMaxDynamicSharedMemorySize, SMEM_BYTES);

    k_init<<<512, 256>>>();
    k_prep_w<<<8192, 256>>>(Wih_f, Whh_f, Wih_b, Whh_b);
    k_prep_b<<<64, 256>>>(bih_f, bhh_f, bih_b, bhh_b);
    k_prep_x<<<8192, 256>>>(x);
    k_lstm<<<NB, NTHR, SMEM_BYTES>>>((float*)d_out);
}

// round 7
// speedup vs baseline: 1.3964x; 1.0263x over previous
#include <cuda_runtime.h>
#include <cuda_fp16.h>
#include <cstdint>
#include <cstddef>

// Problem constants
#define BATCH 64
#define TT    512
#define HH    1024
#define NB    128      // persistent CTAs (4 gemms x 32 n-blocks)
#define NTHR  256
#define KC    64       // K-chunk (halves)
#define NCHUNK 32      // 2048 / 64
#define NSTAGE 4
#define RS    72       // smem row stride in halves (144B; 16B-bank stride 9 -> conflict-free)
#define STAGEB 27648   // (64 + 128) rows * 144B
#define AREG   9216    // A region bytes within stage (64*144)
#define GSMO   (NSTAGE * STAGEB)              // 110592: gate overlay region
#define SMEM_BYTES (GSMO + 64 * 132 * 4)      // 144384

// ---------------- device scratch ----------------
static __device__ __half g_W[(size_t)4 * 4096 * 2048];   // fused+permuted weights fp16 (64 MB)
static __device__ float  g_bias[4 * 4096];               // bih+bhh fused, permuted
static __device__ __half g_x16[(size_t)TT * BATCH * HH]; // x as [t][b][k] fp16 (64 MB)
static __device__ __half g_h0[2][BATCH * HH];            // carry h (layer0 backward), ping-pong
static __device__ float  g_c0[2][BATCH * HH];
static __device__ __half g_h1[2][BATCH * HH];            // carry h (layer1 backward)
static __device__ float  g_c1[2][BATCH * HH];
static __device__ __half g_hf0[2][BATCH * HH];           // layer0 forward h -> layer1 input
static __device__ unsigned g_bar_arrive;
static __device__ unsigned g_bar_gen;

// ---------------- PTX helpers ----------------
__device__ __forceinline__ uint32_t smem_u32(const void* p) {
    uint32_t a;
    asm("{ .reg .u64 t; cvta.to.shared.u64 t, %1; cvt.u32.u64 %0, t; }" : "=r"(a) : "l"(p));
    return a;
}
__device__ __forceinline__ void cp16(uint32_t saddr, const void* gptr) {
    asm volatile("cp.async.cg.shared.global [%0], [%1], 16;\n" :: "r"(saddr), "l"(gptr));
}
__device__ __forceinline__ void cp_commit() {
    asm volatile("cp.async.commit_group;\n" ::: "memory");
}
__device__ __forceinline__ void cp_wait2() {
    asm volatile("cp.async.wait_group 2;\n" ::: "memory");
}
__device__ __forceinline__ void cp_wait0() {
    asm volatile("cp.async.wait_group 0;\n" ::: "memory");
}
__device__ __forceinline__ void ldsm4(uint32_t* r, uint32_t addr) {
    asm volatile("ldmatrix.sync.aligned.m8n8.x4.shared.b16 {%0,%1,%2,%3}, [%4];"
                 : "=r"(r[0]), "=r"(r[1]), "=r"(r[2]), "=r"(r[3]) : "r"(addr));
}
__device__ __forceinline__ void mma16816(float* d, const uint32_t* a, const uint32_t* b) {
    asm volatile(
        "mma.sync.aligned.m16n8k16.row.col.f32.f16.f16.f32 "
        "{%0,%1,%2,%3}, {%4,%5,%6,%7}, {%8,%9}, {%0,%1,%2,%3};\n"
        : "+f"(d[0]), "+f"(d[1]), "+f"(d[2]), "+f"(d[3])
        : "r"(a[0]), "r"(a[1]), "r"(a[2]), "r"(a[3]), "r"(b[0]), "r"(b[1]));
}

// Grid barrier (cumulative counter; reset by k_prep each launch).
__device__ __forceinline__ void gridbar(int target) {
    __syncthreads();
    __threadfence();
    if (threadIdx.x == 0) {
        unsigned my = atomicAdd(&g_bar_arrive, 1u) + 1u;
        if (my == (unsigned)(NB * target)) {
            atomicExch(&g_bar_gen, (unsigned)target);
        } else {
            volatile unsigned* vg = &g_bar_gen;
            while (*vg < (unsigned)target) { }
        }
    }
    __syncthreads();
}

// ---------------- merged preprocessing ----------------
// Weights: g_W[gm][n'][k]; n' = nct*128 + gate*32 + u; k<1024 from Wih (K-reversed for
// gm==1, folding x's feature reversal), else Whh. Plus bias fuse, x transpose, state init.
__global__ void k_prep(const float* __restrict__ x,
                       const float* __restrict__ Wih_f, const float* __restrict__ Whh_f,
                       const float* __restrict__ bih_f, const float* __restrict__ bhh_f,
                       const float* __restrict__ Wih_b, const float* __restrict__ Whh_b,
                       const float* __restrict__ bih_b, const float* __restrict__ bhh_b) {
    const size_t gstride = (size_t)gridDim.x * blockDim.x;
    const size_t gtid = (size_t)blockIdx.x * blockDim.x + threadIdx.x;

    // weights
    const size_t wtotal = (size_t)4 * 4096 * 2048;
    for (size_t idx = gtid; idx < wtotal; idx += gstride) {
        int k  = (int)(idx & 2047);
        int np = (int)((idx >> 11) & 4095);
        int gm = (int)(idx >> 23);
        int gate = (np & 127) >> 5;
        int u    = np & 31;
        int nct  = np >> 7;
        int n = gate * 1024 + nct * 32 + u;
        int layer = gm >> 1;
        bool bwd  = (gm & 1) != 0;
        const float* Wih = bwd ? Wih_b : Wih_f;
        const float* Whh = bwd ? Whh_b : Whh_f;
        float v;
        if (k < 1024) {
            int kk = (gm == 1) ? (1023 - k) : k;
            v = Wih[((size_t)layer * 4096 + n) * 1024 + kk];
        } else {
            v = Whh[((size_t)layer * 4096 + n) * 1024 + (k - 1024)];
        }
        g_W[idx] = __float2half_rn(v);
    }
    // x: (B,T,H) fp32 -> [t][b][k] fp16
    const size_t xtotal = (size_t)TT * BATCH * HH;
    for (size_t idx = gtid; idx < xtotal; idx += gstride) {
        int k = (int)(idx & 1023);
        int b = (int)((idx >> 10) & 63);
        int t = (int)(idx >> 16);
        g_x16[idx] = __float2half_rn(x[((size_t)b * TT + t) * HH + k]);
    }
    // bias
    for (size_t idx = gtid; idx < 16384; idx += gstride) {
        int np = (int)(idx & 4095), gm = (int)(idx >> 12);
        int gate = (np & 127) >> 5, u = np & 31, nct = np >> 7;
        int n = gate * 1024 + nct * 32 + u;
        int layer = gm >> 1;
        bool bwd = (gm & 1) != 0;
        const float* bi = bwd ? bih_b : bih_f;
        const float* bh = bwd ? bhh_b : bhh_f;
        g_bias[idx] = bi[layer * 4096 + n] + bh[layer * 4096 + n];
    }
    // state init + barrier reset
    for (size_t idx = gtid; idx < 2 * BATCH * HH; idx += gstride) {
        ((unsigned short*)g_h0)[idx]  = 0;
        ((unsigned short*)g_h1)[idx]  = 0;
        ((unsigned short*)g_hf0)[idx] = 0;
        ((float*)g_c0)[idx] = 0.f;
        ((float*)g_c1)[idx] = 0.f;
    }
    if (gtid == 0) { g_bar_arrive = 0u; g_bar_gen = 0u; }
}

// ---------------- chunk loaders ----------------
__device__ __forceinline__ void load_A(uint32_t stb, int nk, const __half* a1,
                                       const __half* a2, int tid) {
    const int koff = nk * KC;
    const __half* ap = (koff < 1024) ? (a1 + koff) : (a2 + (koff - 1024));
    #pragma unroll
    for (int j = 0; j < 2; ++j) {
        int idx = tid + j * NTHR;           // 512 ops: 64 rows x 8 segs
        int row = idx >> 3, seg = idx & 7;
        cp16(stb + row * 144 + seg * 16, ap + row * HH + seg * 8);
    }
}
__device__ __forceinline__ void load_W(uint32_t stb, int nk, const __half* wbase, int tid) {
    const __half* wp = wbase + nk * KC;
    #pragma unroll
    for (int j = 0; j < 4; ++j) {
        int idx = tid + j * NTHR;           // 1024 ops: 128 rows x 8 segs
        int row = idx >> 3, seg = idx & 7;
        cp16(stb + AREG + row * 144 + seg * 16, wp + (size_t)row * 2048 + seg * 8);
    }
}

// ---------------- persistent LSTM kernel ----------------
// 128 CTAs: gm = blockIdx.x>>5 in {f0,b0,f1,b1}; nct = blockIdx.x&31 owns 128 N-cols.
// Iteration it: layer0(t=it) || layer1(t=it-1); 1 grid barrier per iteration.
__global__ void __launch_bounds__(NTHR, 1) k_lstm(float* __restrict__ dout) {
    extern __shared__ __align__(16) unsigned char sm[];
    const uint32_t smb = smem_u32(sm);
    float* gsm = (float*)(sm + GSMO);       // 64 x 132 fp32 gate overlay (separate region)

    const int tid  = threadIdx.x;
    const int lane = tid & 31;
    const int warp = tid >> 5;
    const int m0 = (warp >> 2) * 32;        // warp tile 32(m) x 32(n); 2m x 4n warps
    const int n0 = (warp & 3) * 32;
    const int gm   = blockIdx.x >> 5;
    const int nct  = blockIdx.x & 31;

    const __half* wbase = g_W + ((size_t)(gm * 4096 + nct * 128)) * 2048;
    const float*  bp    = g_bias + gm * 4096 + nct * 128;

    float* out   = dout;
    float* cout  = dout + (size_t)67108864;   // B*T*2H
    float* outL  = dout + (size_t)134217728;  // 2*B*T*2H
    float* coutL = outL + 131072;             // B*2H

    // ldmatrix per-lane base offsets (bytes)
    const int mat = lane >> 3, mr = lane & 7;
    const uint32_t aoffL = (uint32_t)((m0 + (mat & 1) * 8 + mr) * 144 + (mat >> 1) * 16);
    const uint32_t woffL = (uint32_t)((n0 + (mat >> 1) * 8 + mr) * 144 + (mat & 1) * 16);

    // pre-loop: prefetch W chunks 0..2 into stages 0..2
    #pragma unroll
    for (int pc = 0; pc < 3; ++pc) { load_W(smb + pc * STAGEB, pc, wbase, tid); cp_commit(); }

    #pragma unroll 1
    for (int it = 0; it <= TT; ++it) {
        const int ri = it & 1, wi = ri ^ 1;
        const bool active = (gm < 2) ? (it < TT) : (it >= 1);
        if (active) {
            const int t = (gm < 2) ? it : (it - 1);
            const __half* a1;
            const __half* a2;
            if (gm < 2)       { a1 = g_x16 + (size_t)t * (BATCH * HH); a2 = g_h0[ri]; }
            else if (gm == 2) { a1 = g_hf0[ri];                        a2 = g_h1[ri]; }
            else              { a1 = g_h0[ri];                         a2 = g_h1[ri]; }

            // A for chunks 0..2 (W already prefetched before the barrier)
            #pragma unroll
            for (int pc = 0; pc < 3; ++pc) { load_A(smb + pc * STAGEB, pc, a1, a2, tid); cp_commit(); }

            float acc[2][4][4];
            #pragma unroll
            for (int a = 0; a < 2; ++a)
                #pragma unroll
                for (int b = 0; b < 4; ++b)
                    #pragma unroll
                    for (int c = 0; c < 4; ++c) acc[a][b][c] = 0.f;

            // ---- K loop: 32 chunks, 4-stage cp.async pipeline, frag double-buffer ----
            #pragma unroll 1
            for (int kc = 0; kc < NCHUNK; ++kc) {
                cp_wait2();        // chunk kc fully landed (A+W)
                __syncthreads();   // all warps done with mma(kc-1); stage (kc-1)&3 reusable
                {
                    const int nk = kc + 3;
                    if (nk < NCHUNK) {
                        uint32_t stb = smb + (nk & 3) * STAGEB;
                        load_A(stb, nk, a1, a2, tid);
                        load_W(stb, nk, wbase, tid);
                    }
                    cp_commit();   // always commit (uniform group counts)
                }
                const uint32_t Ab = smb + (kc & 3) * STAGEB;
                const uint32_t Wb = Ab + AREG;
                uint32_t af[2][2][4], bf[2][2][4];
                ldsm4(af[0][0], Ab + aoffL);
                ldsm4(af[0][1], Ab + aoffL + 2304);
                ldsm4(bf[0][0], Wb + woffL);
                ldsm4(bf[0][1], Wb + woffL + 2304);
                #pragma unroll
                for (int ks = 0; ks < 4; ++ks) {
                    const int cb = ks & 1, nb = cb ^ 1;
                    if (ks < 3) {
                        const uint32_t ko = (uint32_t)((ks + 1) * 32);
                        ldsm4(af[nb][0], Ab + aoffL + ko);
                        ldsm4(af[nb][1], Ab + aoffL + 2304 + ko);
                        ldsm4(bf[nb][0], Wb + woffL + ko);
                        ldsm4(bf[nb][1], Wb + woffL + 2304 + ko);
                    }
                    #pragma unroll
                    for (int mt = 0; mt < 2; ++mt)
                        #pragma unroll
                        for (int nt = 0; nt < 4; ++nt)
                            mma16816(acc[mt][nt], af[cb][mt], &bf[cb][nt >> 1][(nt & 1) * 2]);
                }
            }
            __syncthreads();  // all stage reads done

            // prefetch next iteration's W chunks 0..2 (overlaps epilogue + grid barrier)
            #pragma unroll
            for (int pc = 0; pc < 3; ++pc) { load_W(smb + pc * STAGEB, pc, wbase, tid); cp_commit(); }

            // ---- gates to separate smem overlay ----
            #pragma unroll
            for (int mt = 0; mt < 2; ++mt)
                #pragma unroll
                for (int nt = 0; nt < 4; ++nt)
                    #pragma unroll
                    for (int r = 0; r < 4; ++r) {
                        int row = m0 + mt * 16 + (lane >> 2) + ((r & 2) ? 8 : 0);
                        int col = n0 + nt * 8 + ((lane & 3) << 1) + (r & 1);
                        gsm[row * 132 + col] = acc[mt][nt][r];
                    }
            __syncthreads();

            // ---- cell epilogue: 64 batches x 32 hidden units ----
            for (int idx = tid; idx < BATCH * 32; idx += NTHR) {
                int bb = idx >> 5, ul = idx & 31;
                int uglob = nct * 32 + ul;
                int s = bb * HH + uglob;
                float gi = gsm[bb * 132 + ul]      + bp[ul];
                float gf = gsm[bb * 132 + 32 + ul] + bp[32 + ul];
                float gg = gsm[bb * 132 + 64 + ul] + bp[64 + ul];
                float go = gsm[bb * 132 + 96 + ul] + bp[96 + ul];
                float si = 1.f / (1.f + __expf(-gi));
                float sf = 1.f / (1.f + __expf(-gf));
                float so = 1.f / (1.f + __expf(-go));
                float tg = tanhf(gg);
                float cp_ = (gm < 2) ? __ldcg(&g_c0[ri][s]) : __ldcg(&g_c1[ri][s]);
                float cn = sf * cp_ + si * tg;
                float h  = so * tanhf(cn);
                if (gm == 0) {
                    g_hf0[wi][s] = __float2half_rn(h);
                } else if (gm == 1) {
                    g_h0[wi][s] = __float2half_rn(h);
                    g_c0[wi][s] = cn;
                } else {
                    size_t ob = ((size_t)bb * TT + t) * 2048 + (gm == 3 ? 1024 : 0) + uglob;
                    out[ob]  = h;
                    cout[ob] = cn;
                    if (t == TT - 1) {
                        int o2 = bb * 2048 + (gm == 3 ? 1024 : 0) + uglob;
                        outL[o2]  = h;
                        coutL[o2] = cn;
                    }
                    if (gm == 3) {
                        g_h1[wi][s] = __float2half_rn(h);
                        g_c1[wi][s] = cn;
                    }
                }
            }
        }
        gridbar(it + 1);
    }
    cp_wait0();   // drain leftover W prefetch before exit
}

// ---------------- launcher ----------------
extern "C" void kernel_launch(void* const* d_in, const int* in_sizes, int n_in,
                              void* d_out, int out_size) {
    (void)in_sizes; (void)n_in; (void)out_size;
    const float* x     = (const float*)d_in[0];
    const float* Wih_f = (const float*)d_in[1];
    const float* Whh_f = (const float*)d_in[2];
    const float* bih_f = (const float*)d_in[3];
    const float* bhh_f = (const float*)d_in[4];
    const float* Wih_b = (const float*)d_in[5];
    const float* Whh_b = (const float*)d_in[6];
    const float* bih_b = (const float*)d_in[7];
    const float* bhh_b = (const float*)d_in[8];

    cudaFuncSetAttribute(k_lstm, cudaFuncAttributeMaxDynamicSharedMemorySize, SMEM_BYTES);

    k_prep<<<8192, 256>>>(x, Wih_f, Whh_f, bih_f, bhh_f, Wih_b, Whh_b, bih_b, bhh_b);
    k_lstm<<<NB, NTHR, SMEM_BYTES>>>((float*)d_out);
}

// round 11
// speedup vs baseline: 1.4189x; 1.0161x over previous
#include <cuda_runtime.h>
#include <cuda_fp16.h>
#include <cstdint>
#include <cstddef>

// Problem constants
#define BATCH 64
#define TT    512
#define HH    1024
#define NB    256      // persistent CTAs (4 gemms x 64 n-blocks), 2 co-resident per SM
#define NTHR  256
#define KC    64       // K-chunk (halves)
#define NCHUNK 32      // 2048 / 64
#define NSTAGE 4
#define STAGEB 18432   // (64 A + 64 W) rows * 144B
#define AREG   9216    // A region bytes within stage (64*144)
#define GSMO   (NSTAGE * STAGEB)              // 73728: gate overlay region
#define SMEM_BYTES (GSMO + 64 * 68 * 4)       // 91136 -> 2 CTAs/SM

// ---------------- device scratch ----------------
static __device__ __half g_W[(size_t)4 * 4096 * 2048];   // fused+permuted weights fp16 (64 MB)
static __device__ float  g_bias[4 * 4096];               // bih+bhh fused, permuted
static __device__ __half g_x16[(size_t)TT * BATCH * HH]; // x as [t][b][k] fp16 (64 MB)
static __device__ __half g_h0[2][BATCH * HH];            // carry h (layer0 backward), ping-pong
static __device__ float  g_c0[2][BATCH * HH];
static __device__ __half g_h1[2][BATCH * HH];            // carry h (layer1 backward)
static __device__ float  g_c1[2][BATCH * HH];
static __device__ __half g_hf0[2][BATCH * HH];           // layer0 forward h -> layer1 input
static __device__ unsigned g_bar_arrive;
static __device__ unsigned g_bar_gen;

// ---------------- PTX helpers ----------------
__device__ __forceinline__ uint32_t smem_u32(const void* p) {
    uint32_t a;
    asm("{ .reg .u64 t; cvta.to.shared.u64 t, %1; cvt.u32.u64 %0, t; }" : "=r"(a) : "l"(p));
    return a;
}
__device__ __forceinline__ void cp16(uint32_t saddr, const void* gptr) {
    asm volatile("cp.async.cg.shared.global [%0], [%1], 16;\n" :: "r"(saddr), "l"(gptr));
}
__device__ __forceinline__ void cp_commit() {
    asm volatile("cp.async.commit_group;\n" ::: "memory");
}
__device__ __forceinline__ void cp_wait2() {
    asm volatile("cp.async.wait_group 2;\n" ::: "memory");
}
__device__ __forceinline__ void cp_wait0() {
    asm volatile("cp.async.wait_group 0;\n" ::: "memory");
}
__device__ __forceinline__ void ldsm4(uint32_t* r, uint32_t addr) {
    asm volatile("ldmatrix.sync.aligned.m8n8.x4.shared.b16 {%0,%1,%2,%3}, [%4];"
                 : "=r"(r[0]), "=r"(r[1]), "=r"(r[2]), "=r"(r[3]) : "r"(addr));
}
__device__ __forceinline__ void mma16816(float* d, const uint32_t* a, const uint32_t* b) {
    asm volatile(
        "mma.sync.aligned.m16n8k16.row.col.f32.f16.f16.f32 "
        "{%0,%1,%2,%3}, {%4,%5,%6,%7}, {%8,%9}, {%0,%1,%2,%3};\n"
        : "+f"(d[0]), "+f"(d[1]), "+f"(d[2]), "+f"(d[3])
        : "r"(a[0]), "r"(a[1]), "r"(a[2]), "r"(a[3]), "r"(b[0]), "r"(b[1]));
}

// Grid barrier (cumulative counter; reset by k_prep each launch).
__device__ __forceinline__ void gridbar(int target) {
    __syncthreads();
    __threadfence();
    if (threadIdx.x == 0) {
        unsigned my = atomicAdd(&g_bar_arrive, 1u) + 1u;
        if (my == (unsigned)(NB * target)) {
            atomicExch(&g_bar_gen, (unsigned)target);
        } else {
            volatile unsigned* vg = &g_bar_gen;
            while (*vg < (unsigned)target) { }
        }
    }
    __syncthreads();
}

// ---------------- merged preprocessing ----------------
// Weights: g_W[gm][n'][k]; n' = nct*64 + gate*16 + u (nct 0..63 owns 16 units x 4 gates);
// k<1024 from Wih (K-reversed for gm==1, folding x's feature reversal), else Whh.
__global__ void k_prep(const float* __restrict__ x,
                       const float* __restrict__ Wih_f, const float* __restrict__ Whh_f,
                       const float* __restrict__ bih_f, const float* __restrict__ bhh_f,
                       const float* __restrict__ Wih_b, const float* __restrict__ Whh_b,
                       const float* __restrict__ bih_b, const float* __restrict__ bhh_b) {
    const size_t gstride = (size_t)gridDim.x * blockDim.x;
    const size_t gtid = (size_t)blockIdx.x * blockDim.x + threadIdx.x;

    const size_t wtotal = (size_t)4 * 4096 * 2048;
    for (size_t idx = gtid; idx < wtotal; idx += gstride) {
        int k  = (int)(idx & 2047);
        int np = (int)((idx >> 11) & 4095);
        int gm = (int)(idx >> 23);
        int loc  = np & 63;
        int nct  = np >> 6;
        int gate = loc >> 4;
        int u    = loc & 15;
        int n = gate * 1024 + nct * 16 + u;
        int layer = gm >> 1;
        bool bwd  = (gm & 1) != 0;
        const float* Wih = bwd ? Wih_b : Wih_f;
        const float* Whh = bwd ? Whh_b : Whh_f;
        float v;
        if (k < 1024) {
            int kk = (gm == 1) ? (1023 - k) : k;
            v = Wih[((size_t)layer * 4096 + n) * 1024 + kk];
        } else {
            v = Whh[((size_t)layer * 4096 + n) * 1024 + (k - 1024)];
        }
        g_W[idx] = __float2half_rn(v);
    }
    const size_t xtotal = (size_t)TT * BATCH * HH;
    for (size_t idx = gtid; idx < xtotal; idx += gstride) {
        int k = (int)(idx & 1023);
        int b = (int)((idx >> 10) & 63);
        int t = (int)(idx >> 16);
        g_x16[idx] = __float2half_rn(x[((size_t)b * TT + t) * HH + k]);
    }
    for (size_t idx = gtid; idx < 16384; idx += gstride) {
        int np = (int)(idx & 4095), gm = (int)(idx >> 12);
        int loc = np & 63, nct = np >> 6;
        int gate = loc >> 4, u = loc & 15;
        int n = gate * 1024 + nct * 16 + u;
        int layer = gm >> 1;
        bool bwd = (gm & 1) != 0;
        const float* bi = bwd ? bih_b : bih_f;
        const float* bh = bwd ? bhh_b : bhh_f;
        g_bias[idx] = bi[layer * 4096 + n] + bh[layer * 4096 + n];
    }
    for (size_t idx = gtid; idx < 2 * BATCH * HH; idx += gstride) {
        ((unsigned short*)g_h0)[idx]  = 0;
        ((unsigned short*)g_h1)[idx]  = 0;
        ((unsigned short*)g_hf0)[idx] = 0;
        ((float*)g_c0)[idx] = 0.f;
        ((float*)g_c1)[idx] = 0.f;
    }
    if (gtid == 0) { g_bar_arrive = 0u; g_bar_gen = 0u; }
}

// ---------------- chunk loaders ----------------
__device__ __forceinline__ void load_A(uint32_t stb, int nk, const __half* a1,
                                       const __half* a2, int tid) {
    const int koff = nk * KC;
    const __half* ap = (koff < 1024) ? (a1 + koff) : (a2 + (koff - 1024));
    #pragma unroll
    for (int j = 0; j < 2; ++j) {
        int idx = tid + j * NTHR;           // 512 ops: 64 rows x 8 segs
        int row = idx >> 3, seg = idx & 7;
        cp16(stb + row * 144 + seg * 16, ap + row * HH + seg * 8);
    }
}
__device__ __forceinline__ void load_W(uint32_t stb, int nk, const __half* wbase, int tid) {
    const __half* wp = wbase + nk * KC;
    #pragma unroll
    for (int j = 0; j < 2; ++j) {
        int idx = tid + j * NTHR;           // 512 ops: 64 rows x 8 segs
        int row = idx >> 3, seg = idx & 7;
        cp16(stb + AREG + row * 144 + seg * 16, wp + (size_t)row * 2048 + seg * 8);
    }
}

// ---------------- persistent LSTM kernel ----------------
// 256 CTAs (2/SM): gm = blockIdx.x>>6 in {f0,b0,f1,b1}; nct = blockIdx.x&63 owns 64 N-cols.
// Iteration it: layer0(t=it) || layer1(t=it-1); 1 grid barrier per iteration.
__global__ void __launch_bounds__(NTHR, 2) k_lstm(float* __restrict__ dout) {
    extern __shared__ __align__(16) unsigned char sm[];
    const uint32_t smb = smem_u32(sm);
    float* gsm = (float*)(sm + GSMO);       // 64 x 68 fp32 gate overlay

    const int tid  = threadIdx.x;
    const int lane = tid & 31;
    const int warp = tid >> 5;
    const int m0 = (warp >> 2) * 32;        // warp tile 32(m) x 16(n); 2m x 4n warps
    const int n0 = (warp & 3) * 16;
    const int gm   = blockIdx.x >> 6;
    const int nct  = blockIdx.x & 63;

    const __half* wbase = g_W + ((size_t)(gm * 4096 + nct * 64)) * 2048;
    const float*  bp    = g_bias + gm * 4096 + nct * 64;

    float* out   = dout;
    float* cout  = dout + (size_t)67108864;   // B*T*2H
    float* outL  = dout + (size_t)134217728;  // 2*B*T*2H
    float* coutL = outL + 131072;             // B*2H

    // ldmatrix per-lane base offsets (bytes)
    const int mat = lane >> 3, mr = lane & 7;
    const uint32_t aoffL = (uint32_t)((m0 + (mat & 1) * 8 + mr) * 144 + (mat >> 1) * 16);
    const uint32_t woffL = (uint32_t)((n0 + (mat >> 1) * 8 + mr) * 144 + (mat & 1) * 16);

    // pre-loop: prefetch W chunks 0..2 into stages 0..2
    #pragma unroll
    for (int pc = 0; pc < 3; ++pc) { load_W(smb + pc * STAGEB, pc, wbase, tid); cp_commit(); }

    #pragma unroll 1
    for (int it = 0; it <= TT; ++it) {
        const int ri = it & 1, wi = ri ^ 1;
        const bool active = (gm < 2) ? (it < TT) : (it >= 1);
        if (active) {
            const int t = (gm < 2) ? it : (it - 1);
            const __half* a1;
            const __half* a2;
            if (gm < 2)       { a1 = g_x16 + (size_t)t * (BATCH * HH); a2 = g_h0[ri]; }
            else if (gm == 2) { a1 = g_hf0[ri];                        a2 = g_h1[ri]; }
            else              { a1 = g_h0[ri];                         a2 = g_h1[ri]; }

            // A for chunks 0..2 (W already prefetched before the barrier)
            #pragma unroll
            for (int pc = 0; pc < 3; ++pc) { load_A(smb + pc * STAGEB, pc, a1, a2, tid); cp_commit(); }

            float acc[2][2][4];
            #pragma unroll
            for (int a = 0; a < 2; ++a)
                #pragma unroll
                for (int b = 0; b < 2; ++b)
                    #pragma unroll
                    for (int c = 0; c < 4; ++c) acc[a][b][c] = 0.f;

            // ---- K loop: 32 chunks, 4-stage cp.async pipeline, frag double-buffer ----
            #pragma unroll 1
            for (int kc = 0; kc < NCHUNK; ++kc) {
                cp_wait2();        // chunk kc fully landed (A+W)
                __syncthreads();   // all warps done with mma(kc-1); stage (kc-1)&3 reusable
                {
                    const int nk = kc + 3;
                    if (nk < NCHUNK) {
                        uint32_t stb = smb + (nk & 3) * STAGEB;
                        load_A(stb, nk, a1, a2, tid);
                        load_W(stb, nk, wbase, tid);
                    }
                    cp_commit();   // always commit (uniform group counts)
                }
                const uint32_t Ab = smb + (kc & 3) * STAGEB;
                const uint32_t Wb = Ab + AREG;
                uint32_t af[2][2][4], bf[2][4];
                ldsm4(af[0][0], Ab + aoffL);
                ldsm4(af[0][1], Ab + aoffL + 2304);
                ldsm4(bf[0],    Wb + woffL);
                #pragma unroll
                for (int ks = 0; ks < 4; ++ks) {
                    const int cb = ks & 1, nb = cb ^ 1;
                    if (ks < 3) {
                        const uint32_t ko = (uint32_t)((ks + 1) * 32);
                        ldsm4(af[nb][0], Ab + aoffL + ko);
                        ldsm4(af[nb][1], Ab + aoffL + 2304 + ko);
                        ldsm4(bf[nb],    Wb + woffL + ko);
                    }
                    #pragma unroll
                    for (int mt = 0; mt < 2; ++mt)
                        #pragma unroll
                        for (int nt = 0; nt < 2; ++nt)
                            mma16816(acc[mt][nt], af[cb][mt], &bf[cb][nt * 2]);
                }
            }
            __syncthreads();  // all stage reads done

            // prefetch next iteration's W chunks 0..2 (overlaps epilogue + grid barrier)
            #pragma unroll
            for (int pc = 0; pc < 3; ++pc) { load_W(smb + pc * STAGEB, pc, wbase, tid); cp_commit(); }

            // ---- gates to smem overlay (64 x 68 fp32) ----
            #pragma unroll
            for (int mt = 0; mt < 2; ++mt)
                #pragma unroll
                for (int nt = 0; nt < 2; ++nt)
                    #pragma unroll
                    for (int r = 0; r < 4; ++r) {
                        int row = m0 + mt * 16 + (lane >> 2) + ((r & 2) ? 8 : 0);
                        int col = n0 + nt * 8 + ((lane & 3) << 1) + (r & 1);
                        gsm[row * 68 + col] = acc[mt][nt][r];
                    }
            __syncthreads();

            // ---- cell epilogue: 64 batches x 16 hidden units ----
            for (int idx = tid; idx < BATCH * 16; idx += NTHR) {
                int bb = idx >> 4, ul = idx & 15;
                int uglob = nct * 16 + ul;
                int s = bb * HH + uglob;
                float gi = gsm[bb * 68 + ul]      + bp[ul];
                float gf = gsm[bb * 68 + 16 + ul] + bp[16 + ul];
                float gg = gsm[bb * 68 + 32 + ul] + bp[32 + ul];
                float go = gsm[bb * 68 + 48 + ul] + bp[48 + ul];
                float si = 1.f / (1.f + __expf(-gi));
                float sf = 1.f / (1.f + __expf(-gf));
                float so = 1.f / (1.f + __expf(-go));
                float tg = tanhf(gg);
                float cp_ = (gm < 2) ? __ldcg(&g_c0[ri][s]) : __ldcg(&g_c1[ri][s]);
                float cn = sf * cp_ + si * tg;
                float h  = so * tanhf(cn);
                if (gm == 0) {
                    g_hf0[wi][s] = __float2half_rn(h);
                } else if (gm == 1) {
                    g_h0[wi][s] = __float2half_rn(h);
                    g_c0[wi][s] = cn;
                } else {
                    size_t ob = ((size_t)bb * TT + t) * 2048 + (gm == 3 ? 1024 : 0) + uglob;
                    out[ob]  = h;
                    cout[ob] = cn;
                    if (t == TT - 1) {
                        int o2 = bb * 2048 + (gm == 3 ? 1024 : 0) + uglob;
                        outL[o2]  = h;
                        coutL[o2] = cn;
                    }
                    if (gm == 3) {
                        g_h1[wi][s] = __float2half_rn(h);
                        g_c1[wi][s] = cn;
                    }
                }
            }
        }
        gridbar(it + 1);
    }
    cp_wait0();   // drain leftover W prefetch before exit
}

// ---------------- launcher ----------------
extern "C" void kernel_launch(void* const* d_in, const int* in_sizes, int n_in,
                              void* d_out, int out_size) {
    (void)in_sizes; (void)n_in; (void)out_size;
    const float* x     = (const float*)d_in[0];
    const float* Wih_f = (const float*)d_in[1];
    const float* Whh_f = (const float*)d_in[2];
    const float* bih_f = (const float*)d_in[3];
    const float* bhh_f = (const float*)d_in[4];
    const float* Wih_b = (const float*)d_in[5];
    const float* Whh_b = (const float*)d_in[6];
    const float* bih_b = (const float*)d_in[7];
    const float* bhh_b = (const float*)d_in[8];

    cudaFuncSetAttribute(k_lstm, cudaFuncAttributeMaxDynamicSharedMemorySize, SMEM_BYTES);

    k_prep<<<8192, 256>>>(x, Wih_f, Whh_f, bih_f, bhh_f, Wih_b, Whh_b, bih_b, bhh_b);
    k_lstm<<<NB, NTHR, SMEM_BYTES>>>((float*)d_out);
}